// round 14
// baseline (speedup 1.0000x reference)
#include <cuda_runtime.h>
#include <cuda_fp16.h>
#include <mma.h>
#include <math_constants.h>
#include <cstdint>

using namespace nvcuda;

#define S_LEN 4096
#define DIM   2048
#define HEADS 16
#define HD    128
#define GK    2048
#define BM    128
#define BN    128
#define BKC   64
#define NKC   (GK / BKC)    // 32
#define FSLD  72            // gemm smem row stride (fp16)

// ---------------- scratch (allocation-free rule: __device__ globals) ----------
__device__ __half g_Q16[HEADS * S_LEN * HD];
__device__ __half g_K16[HEADS * S_LEN * HD];
__device__ __half g_V16[HEADS * S_LEN * HD];
__device__ __half g_O16[S_LEN * DIM];
__device__ __half g_X16[S_LEN * DIM];
__device__ __half g_W16[4][DIM * DIM];

// ---------------- helpers ------------------------------------------------------
__device__ __forceinline__ uint32_t smem_u32(const void* p) {
    uint32_t a;
    asm("{ .reg .u64 t; cvta.to.shared.u64 t, %1; cvt.u32.u64 %0, t; }"
        : "=r"(a) : "l"(p));
    return a;
}
#define CP_ASYNC16(dst_u32, src_ptr) \
    asm volatile("cp.async.cg.shared.global [%0], [%1], 16;" \
        :: "r"(dst_u32), "l"(src_ptr) : "memory")
#define CP_ASYNC_COMMIT() asm volatile("cp.async.commit_group;" ::: "memory")
#define CP_ASYNC_WAIT0()  asm volatile("cp.async.wait_group 0;" ::: "memory")
#define CP_ASYNC_WAIT1()  asm volatile("cp.async.wait_group 1;" ::: "memory")

__device__ __forceinline__ uint32_t pack_h2(__half a, __half b) {
    __half2 t = __halves2half2(a, b);
    return *(uint32_t*)&t;
}

// ============================================================================
// splits
// ============================================================================
__global__ void split_h16(const float4* __restrict__ src,
                          uint2* __restrict__ dst, int n4) {
    int i = blockIdx.x * 256 + threadIdx.x;
    if (i >= n4) return;
    float4 v = src[i];
    uint2 ho;
    ho.x = pack_h2(__float2half(v.x), __float2half(v.y));
    ho.y = pack_h2(__float2half(v.z), __float2half(v.w));
    dst[i] = ho;
}

__global__ void split_h16_w4(const float4* __restrict__ s0,
                             const float4* __restrict__ s1,
                             const float4* __restrict__ s2,
                             const float4* __restrict__ s3,
                             uint2* __restrict__ dst, int n4) {
    int i = blockIdx.x * 256 + threadIdx.x;
    if (i >= n4) return;
    const float4* srcs[4] = {s0, s1, s2, s3};
    float4 v = srcs[blockIdx.y][i];
    uint2 ho;
    ho.x = pack_h2(__float2half(v.x), __float2half(v.y));
    ho.y = pack_h2(__float2half(v.z), __float2half(v.w));
    dst[(size_t)blockIdx.y * n4 + i] = ho;
}

// ============================================================================
// fp16 WMMA GEMM (1-term): C = A * B^T + bias   — 2 CTAs/SM (unchanged R13)
// ============================================================================
#define FTILE_ELEMS (128 * FSLD)
#define FTILE_BYTES (FTILE_ELEMS * 2)          // 18432
#define GEMM_SMEM   (2 * 2 * FTILE_BYTES)      // 73728

template <int MODE, int NFUSE>
__global__ __launch_bounds__(256, 2) void gemm_f16(
    const __half* __restrict__ A,
    const __half* __restrict__ B0, const __half* __restrict__ B1,
    const __half* __restrict__ B2,
    const float* __restrict__ bias0, const float* __restrict__ bias1,
    const float* __restrict__ bias2,
    float* __restrict__ C,
    __half* __restrict__ Ch0, __half* __restrict__ Ch1,
    __half* __restrict__ Ch2,
    int M, int N)
{
    extern __shared__ char smemg[];
    __half* sbuf = (__half*)smemg;
    const uint32_t sb = smem_u32(smemg);

    const __half* B    = B0;
    const float*  bias = bias0;
    __half*       Ch   = Ch0;
    if (NFUSE > 1) {
        if (blockIdx.z == 1) { B = B1; bias = bias1; Ch = Ch1; }
        else if (blockIdx.z == 2) { B = B2; bias = bias2; Ch = Ch2; }
    }

    const int tid  = threadIdx.x;
    const int wid  = tid >> 5;
    const int m0   = blockIdx.y * BM;
    const int n0   = blockIdx.x * BN;
    const int wm   = (wid & 3) * 32;
    const int wn   = (wid >> 2) * 64;

    const __half* srcA = A + (size_t)m0 * GK;
    const __half* srcB = B + (size_t)n0 * GK;

    const int lrow0 = tid >> 3;
    const int lc16  = (tid & 7) * 8;

    auto load_chunk = [&](int kt, int buf) {
        const int kc = kt * BKC;
        const __half* ga = srcA + (size_t)lrow0 * GK + kc + lc16;
        const __half* gb = srcB + (size_t)lrow0 * GK + kc + lc16;
        uint32_t da = sb + buf * (2 * FTILE_BYTES) + (lrow0 * FSLD + lc16) * 2;
        uint32_t db = da + FTILE_BYTES;
        #pragma unroll
        for (int i = 0; i < 4; i++) {
            CP_ASYNC16(da + i * (32 * FSLD * 2), ga + (size_t)(i * 32) * GK);
            CP_ASYNC16(db + i * (32 * FSLD * 2), gb + (size_t)(i * 32) * GK);
        }
    };

    wmma::fragment<wmma::accumulator, 16, 16, 16, float> acc[2][4];
    #pragma unroll
    for (int t = 0; t < 2; t++)
        #pragma unroll
        for (int u = 0; u < 4; u++) wmma::fill_fragment(acc[t][u], 0.0f);

    load_chunk(0, 0);
    CP_ASYNC_COMMIT();
    CP_ASYNC_WAIT0();
    __syncthreads();

    for (int kt = 0; kt < NKC; kt++) {
        const int cur = kt & 1;
        if (kt + 1 < NKC) {
            load_chunk(kt + 1, cur ^ 1);
            CP_ASYNC_COMMIT();
        }

        const __half* pA = sbuf + cur * (2 * FTILE_ELEMS);
        const __half* pB = pA + FTILE_ELEMS;

        #pragma unroll
        for (int ks = 0; ks < 4; ks++) {
            wmma::fragment<wmma::matrix_a, 16, 16, 16, __half, wmma::row_major> ah[2];
            wmma::fragment<wmma::matrix_b, 16, 16, 16, __half, wmma::col_major> bh[4];
            #pragma unroll
            for (int t = 0; t < 2; t++)
                wmma::load_matrix_sync(ah[t], pA + (wm + t * 16) * FSLD + ks * 16, FSLD);
            #pragma unroll
            for (int u = 0; u < 4; u++)
                wmma::load_matrix_sync(bh[u], pB + (wn + u * 16) * FSLD + ks * 16, FSLD);
            #pragma unroll
            for (int t = 0; t < 2; t++)
                #pragma unroll
                for (int u = 0; u < 4; u++)
                    wmma::mma_sync(acc[t][u], ah[t], bh[u], acc[t][u]);
        }

        if (kt + 1 < NKC) CP_ASYNC_WAIT0();
        __syncthreads();
    }

    float* sC = (float*)smemg;
    const int CLD = 132;
    #pragma unroll
    for (int t = 0; t < 2; t++)
        #pragma unroll
        for (int u = 0; u < 4; u++)
            wmma::store_matrix_sync(sC + (wm + t * 16) * CLD + wn + u * 16,
                                    acc[t][u], CLD, wmma::mem_row_major);
    __syncthreads();

    #pragma unroll
    for (int i = 0; i < 16; i++) {
        const int flat4 = tid + i * 256;
        const int row = flat4 >> 5;
        const int c   = (flat4 & 31) * 4;
        float v0 = sC[row * CLD + c + 0] + bias[n0 + c + 0];
        float v1 = sC[row * CLD + c + 1] + bias[n0 + c + 1];
        float v2 = sC[row * CLD + c + 2] + bias[n0 + c + 2];
        float v3 = sC[row * CLD + c + 3] + bias[n0 + c + 3];
        if (MODE == 0) {
            *(float4*)(C + (size_t)(m0 + row) * N + n0 + c) =
                make_float4(v0, v1, v2, v3);
        } else {
            size_t idx = (size_t)blockIdx.x * (size_t)M * 128 + (size_t)(m0 + row) * 128 + c;
            uint2 ho;
            ho.x = pack_h2(__float2half(v0), __float2half(v1));
            ho.y = pack_h2(__float2half(v2), __float2half(v3));
            *(uint2*)(Ch + idx) = ho;
        }
    }
}

// ============================================================================
// fp16 WMMA flash attention (causal) — 128-KEY TILES, 1 CTA/SM, warp tile 32x64.
// SMEM (bytes):
//   Q  fp16 [128][136] @0                    (34816)
//   KV bufs [128][136] @34816 + b*34816      (69632)
//   S  fp32 [128][132] @104448               (67584)
//   P  fp16 [128][136] @172032               (34816)
//   sl @206848 (512), swm @207360 (32)       -> total 207392
// Epilogue fp32 O [128][132] aliases @0 (Q + part of KV0).
// ============================================================================
#define AQ_OFF  0
#define AKV_OFF 34816
#define KVBUF   34816
#define AS_OFF  104448
#define AP_OFF  172032
#define ASL_OFF 206848
#define ASW_OFF 207360
#define ATTN_SMEM 207392
#define QKSCALE 0.08838834764831843f   // 1/sqrt(128)

__global__ __launch_bounds__(256, 1) void flash_attn_f16(
    const __half* __restrict__ Q16, const __half* __restrict__ K16,
    const __half* __restrict__ V16,
    __half* __restrict__ O16)
{
    extern __shared__ char smem[];
    const uint32_t sb = smem_u32(smem);

    __half* sQ  = (__half*)(smem + AQ_OFF);
    float*  sS  = (float*)(smem + AS_OFF);
    __half* sP  = (__half*)(smem + AP_OFF);
    float*  sl  = (float*)(smem + ASL_OFF);
    float*  swm = (float*)(smem + ASW_OFF);
    const int SLD2 = 132;   // S row stride (fp32)
    const int PLD  = 136;   // P row stride (fp16)

    const int tid = threadIdx.x;
    const int wid = tid >> 5;
    const int lane = tid & 31;
    const int qt  = gridDim.x - 1 - blockIdx.x;   // heavy CTAs first
    const int h   = blockIdx.y;
    const int ntiles = qt + 1;                    // 128-key tiles

    const __half* Qh = Q16 + ((size_t)h * S_LEN + (size_t)qt * 128) * HD;
    const __half* Kh = K16 + (size_t)h * S_LEN * HD;
    const __half* Vh = V16 + (size_t)h * S_LEN * HD;

    auto loadQ = [&]() {
        #pragma unroll
        for (int rep = 0; rep < 8; rep++) {
            int id  = tid + rep * 256;            // 0..2047
            int row = id >> 4, cc = (id & 15) * 8;
            CP_ASYNC16(sb + AQ_OFF + (row * 136 + cc) * 2, Qh + (size_t)row * HD + cc);
        }
    };
    auto loadKV = [&](const __half* Tp, int ktile, int buf) {
        const size_t base = (size_t)ktile * 128 * HD;
        #pragma unroll
        for (int rep = 0; rep < 8; rep++) {
            int id  = tid + rep * 256;            // 0..2047
            int row = id >> 4, cc = (id & 15) * 8;
            CP_ASYNC16(sb + AKV_OFF + buf * KVBUF + (row * 136 + cc) * 2,
                       Tp + base + (size_t)row * HD + cc);
        }
    };

    loadQ();
    loadKV(Kh, 0, 0);
    CP_ASYNC_COMMIT();

    wmma::fragment<wmma::accumulator, 16, 16, 16, float> facc[2][4];
    #pragma unroll
    for (int t = 0; t < 2; t++)
        #pragma unroll
        for (int u = 0; u < 4; u++) wmma::fill_fragment(facc[t][u], 0.0f);
    float lrun = 0.0f;
    float Mrun = -1.0e30f;

    const int wm = (wid & 3) * 32;        // warp q-rows
    const int wn = (wid >> 2) * 64;       // warp cols (keys in S phase, d in PV)

    for (int kt = 0; kt < ntiles; kt++) {
        const int cur = kt & 1;
        __half* kvS = (__half*)(smem + AKV_OFF + cur * KVBUF);

        CP_ASYNC_WAIT0();
        __syncthreads();

        // ---- S = Q K^T : warp tile 32x64, 8 accumulators ----
        {
            wmma::fragment<wmma::accumulator, 16, 16, 16, float> accs[2][4];
            #pragma unroll
            for (int t = 0; t < 2; t++)
                #pragma unroll
                for (int u = 0; u < 4; u++) wmma::fill_fragment(accs[t][u], 0.0f);

            #pragma unroll
            for (int ks = 0; ks < 8; ks++) {
                wmma::fragment<wmma::matrix_a, 16, 16, 16, __half, wmma::row_major> ah[2];
                wmma::fragment<wmma::matrix_b, 16, 16, 16, __half, wmma::col_major> bh[4];
                #pragma unroll
                for (int t = 0; t < 2; t++)
                    wmma::load_matrix_sync(ah[t], sQ + (wm + t * 16) * 136 + ks * 16, 136);
                #pragma unroll
                for (int u = 0; u < 4; u++)
                    wmma::load_matrix_sync(bh[u], kvS + (wn + u * 16) * 136 + ks * 16, 136);
                #pragma unroll
                for (int t = 0; t < 2; t++)
                    #pragma unroll
                    for (int u = 0; u < 4; u++)
                        wmma::mma_sync(accs[t][u], ah[t], bh[u], accs[t][u]);
            }
            #pragma unroll
            for (int t = 0; t < 2; t++)
                #pragma unroll
                for (int u = 0; u < 4; u++)
                    wmma::store_matrix_sync(sS + (wm + t * 16) * SLD2 + wn + u * 16,
                                            accs[t][u], SLD2, wmma::mem_row_major);
        }
        __syncthreads();

        // ---- prefetch: V(kt) overwrites K(kt) in buf cur; K(kt+1) -> other buf
        loadKV(Vh, kt, cur);
        CP_ASYNC_COMMIT();
        if (kt + 1 < ntiles) loadKV(Kh, kt + 1, cur ^ 1);
        CP_ASYNC_COMMIT();

        // ---- tile max (CTA-wide) ----
        {
            const float* Srow = sS + (tid >> 1) * SLD2 + (tid & 1) * 64;
            float lm = -1.0e30f;
            #pragma unroll
            for (int j = 0; j < 64; j++) lm = fmaxf(lm, Srow[j]);
            #pragma unroll
            for (int o = 16; o > 0; o >>= 1)
                lm = fmaxf(lm, __shfl_xor_sync(0xffffffffu, lm, o));
            if (lane == 0) swm[wid] = lm;
        }
        __syncthreads();
        float mfs = swm[0];
        #pragma unroll
        for (int w = 1; w < 8; w++) mfs = fmaxf(mfs, swm[w]);
        const float m_sc = mfs * QKSCALE;
        const float Mnew = fmaxf(Mrun, m_sc);
        const float corr = __expf(Mrun - Mnew);
        Mrun = Mnew;

        // ---- softmax: p = exp(s*scale - Mnew), mask, fp16 store ----
        {
            const int row = tid >> 1;
            const int c0  = (tid & 1) * 64;
            const int qglob = qt * 128 + row;
            const int kbase = kt * 128 + c0;
            const bool needMask = (kt == qt);
            const float* Srow = sS + row * SLD2 + c0;
            __half* Pr = sP + row * PLD + c0;
            float psum = 0.0f;
            #pragma unroll
            for (int j = 0; j < 64; j += 2) {
                float p0 = __expf(Srow[j]     * QKSCALE - Mnew);
                float p1 = __expf(Srow[j + 1] * QKSCALE - Mnew);
                if (needMask) {
                    if (kbase + j     > qglob) p0 = 0.0f;
                    if (kbase + j + 1 > qglob) p1 = 0.0f;
                }
                psum += p0 + p1;
                *(uint32_t*)(Pr + j) = pack_h2(__float2half(p0), __float2half(p1));
            }
            psum += __shfl_xor_sync(0xffffffffu, psum, 1);
            lrun = lrun * corr + psum;
        }

        // ---- rescale persistent accumulators (skip when corr==1) ----
        if (corr != 1.0f) {
            #pragma unroll
            for (int t = 0; t < 2; t++)
                #pragma unroll
                for (int u = 0; u < 4; u++)
                    #pragma unroll
                    for (int e = 0; e < facc[t][u].num_elements; e++)
                        facc[t][u].x[e] *= corr;
        }

        CP_ASYNC_WAIT1();          // V ready (next K may still be in flight)
        __syncthreads();           // P visible to all warps

        // ---- O += P V : 128-deep k, 8 accumulators ----
        #pragma unroll
        for (int ks = 0; ks < 8; ks++) {
            wmma::fragment<wmma::matrix_a, 16, 16, 16, __half, wmma::row_major> pa[2];
            wmma::fragment<wmma::matrix_b, 16, 16, 16, __half, wmma::row_major> vb[4];
            #pragma unroll
            for (int t = 0; t < 2; t++)
                wmma::load_matrix_sync(pa[t], sP + (wm + t * 16) * PLD + ks * 16, PLD);
            #pragma unroll
            for (int u = 0; u < 4; u++)
                wmma::load_matrix_sync(vb[u], kvS + (ks * 16) * 136 + wn + u * 16, 136);
            #pragma unroll
            for (int t = 0; t < 2; t++)
                #pragma unroll
                for (int u = 0; u < 4; u++)
                    wmma::mma_sync(facc[t][u], pa[t], vb[u], facc[t][u]);
        }
    }

    CP_ASYNC_WAIT0();
    __syncthreads();

    // ---- epilogue: O = facc / lrun, fp16, write [s][DIM] ----
    float* sO = (float*)(smem + AQ_OFF);      // [128][132] fp32, aliases Q/KV0
    const int OLD = 132;
    #pragma unroll
    for (int t = 0; t < 2; t++)
        #pragma unroll
        for (int u = 0; u < 4; u++)
            wmma::store_matrix_sync(sO + (wm + t * 16) * OLD + wn + u * 16,
                                    facc[t][u], OLD, wmma::mem_row_major);
    if ((tid & 1) == 0) sl[tid >> 1] = lrun;
    __syncthreads();

    {
        const int row = tid >> 1;
        const int c0  = (tid & 1) * 64;
        const float inv = 1.0f / sl[row];
        const size_t dbase = (size_t)(qt * 128 + row) * DIM + (size_t)h * HD + c0;
        #pragma unroll
        for (int j = 0; j < 64; j += 2) {
            float o0 = sO[row * OLD + c0 + j]     * inv;
            float o1 = sO[row * OLD + c0 + j + 1] * inv;
            *(uint32_t*)(O16 + dbase + j) =
                pack_h2(__float2half(o0), __float2half(o1));
        }
    }
}

// ============================================================================
// launch
// ============================================================================
extern "C" void kernel_launch(void* const* d_in, const int* in_sizes, int n_in,
                              void* d_out, int out_size)
{
    const float* X  = (const float*)d_in[0];
    const float* Wq = (const float*)d_in[1];
    const float* bq = (const float*)d_in[2];
    const float* Wk = (const float*)d_in[3];
    const float* bk = (const float*)d_in[4];
    const float* Wv = (const float*)d_in[5];
    const float* bv = (const float*)d_in[6];
    const float* Wo = (const float*)d_in[7];
    const float* bo = (const float*)d_in[8];

    __half *Q16, *K16, *V16, *O16, *X16, *W16;
    cudaGetSymbolAddress((void**)&Q16, g_Q16);
    cudaGetSymbolAddress((void**)&K16, g_K16);
    cudaGetSymbolAddress((void**)&V16, g_V16);
    cudaGetSymbolAddress((void**)&O16, g_O16);
    cudaGetSymbolAddress((void**)&X16, g_X16);
    cudaGetSymbolAddress((void**)&W16, g_W16);

    const int NX4 = S_LEN * DIM / 4;
    const int NW4 = DIM * DIM / 4;

    split_h16<<<(NX4 + 255) / 256, 256>>>((const float4*)X, (uint2*)X16, NX4);
    dim3 gW((NW4 + 255) / 256, 4);
    split_h16_w4<<<gW, 256>>>((const float4*)Wq, (const float4*)Wk,
                              (const float4*)Wv, (const float4*)Wo,
                              (uint2*)W16, NW4);

    cudaFuncSetAttribute(gemm_f16<1, 3>,
        cudaFuncAttributeMaxDynamicSharedMemorySize, GEMM_SMEM);
    cudaFuncSetAttribute(gemm_f16<0, 1>,
        cudaFuncAttributeMaxDynamicSharedMemorySize, GEMM_SMEM);
    cudaFuncSetAttribute(flash_attn_f16,
        cudaFuncAttributeMaxDynamicSharedMemorySize, ATTN_SMEM);

    // Q + K + V projections fused: 1-term each
    dim3 gQKV(DIM / BN, S_LEN / BM, 3);
    gemm_f16<1, 3><<<gQKV, 256, GEMM_SMEM>>>(X16,
        W16 + 0 * (size_t)DIM * DIM, W16 + 1 * (size_t)DIM * DIM,
        W16 + 2 * (size_t)DIM * DIM,
        bq, bk, bv, nullptr, Q16, K16, V16, S_LEN, DIM);

    dim3 gAttn(S_LEN / 128, HEADS);
    flash_attn_f16<<<gAttn, 256, ATTN_SMEM>>>(Q16, K16, V16, O16);

    // O projection: 1-term
    dim3 gGemm(DIM / BN, S_LEN / BM);
    gemm_f16<0, 1><<<gGemm, 256, GEMM_SMEM>>>(O16,
        W16 + 3 * (size_t)DIM * DIM, nullptr, nullptr,
        bo, nullptr, nullptr, (float*)d_out, nullptr, nullptr, nullptr,
        S_LEN, DIM);
}

// round 15
// speedup vs baseline: 1.1020x; 1.1020x over previous
#include <cuda_runtime.h>
#include <cuda_fp16.h>
#include <mma.h>
#include <math_constants.h>
#include <cstdint>

using namespace nvcuda;

#define S_LEN 4096
#define DIM   2048
#define HEADS 16
#define HD    128
#define GK    2048
#define BM    128
#define BN    128
#define BKC   64
#define NKC   (GK / BKC)    // 32
#define FSLD  72            // gemm smem row stride (fp16)

// ---------------- scratch (allocation-free rule: __device__ globals) ----------
__device__ __half g_Q16[HEADS * S_LEN * HD];   // pre-scaled by QKSCALE*log2e
__device__ __half g_K16[HEADS * S_LEN * HD];
__device__ __half g_V16[HEADS * S_LEN * HD];
__device__ __half g_O16[S_LEN * DIM];
__device__ __half g_X16[S_LEN * DIM];
__device__ __half g_W16[4][DIM * DIM];

// ---------------- helpers ------------------------------------------------------
__device__ __forceinline__ uint32_t smem_u32(const void* p) {
    uint32_t a;
    asm("{ .reg .u64 t; cvta.to.shared.u64 t, %1; cvt.u32.u64 %0, t; }"
        : "=r"(a) : "l"(p));
    return a;
}
#define CP_ASYNC16(dst_u32, src_ptr) \
    asm volatile("cp.async.cg.shared.global [%0], [%1], 16;" \
        :: "r"(dst_u32), "l"(src_ptr) : "memory")
#define CP_ASYNC_COMMIT() asm volatile("cp.async.commit_group;" ::: "memory")
#define CP_ASYNC_WAIT0()  asm volatile("cp.async.wait_group 0;" ::: "memory")
#define CP_ASYNC_WAIT1()  asm volatile("cp.async.wait_group 1;" ::: "memory")

__device__ __forceinline__ uint32_t pack_h2(__half a, __half b) {
    __half2 t = __halves2half2(a, b);
    return *(uint32_t*)&t;
}

// ============================================================================
// splits
// ============================================================================
__global__ void split_h16(const float4* __restrict__ src,
                          uint2* __restrict__ dst, int n4) {
    int i = blockIdx.x * 256 + threadIdx.x;
    if (i >= n4) return;
    float4 v = src[i];
    uint2 ho;
    ho.x = pack_h2(__float2half(v.x), __float2half(v.y));
    ho.y = pack_h2(__float2half(v.z), __float2half(v.w));
    dst[i] = ho;
}

__global__ void split_h16_w4(const float4* __restrict__ s0,
                             const float4* __restrict__ s1,
                             const float4* __restrict__ s2,
                             const float4* __restrict__ s3,
                             uint2* __restrict__ dst, int n4) {
    int i = blockIdx.x * 256 + threadIdx.x;
    if (i >= n4) return;
    const float4* srcs[4] = {s0, s1, s2, s3};
    float4 v = srcs[blockIdx.y][i];
    uint2 ho;
    ho.x = pack_h2(__float2half(v.x), __float2half(v.y));
    ho.y = pack_h2(__float2half(v.z), __float2half(v.w));
    dst[(size_t)blockIdx.y * n4 + i] = ho;
}

// ============================================================================
// fp16 WMMA GEMM (1-term): C = (A * B^T + bias) * scale   — 2 CTAs/SM
// ============================================================================
#define FTILE_ELEMS (128 * FSLD)
#define FTILE_BYTES (FTILE_ELEMS * 2)          // 18432
#define GEMM_SMEM   (2 * 2 * FTILE_BYTES)      // 73728

template <int MODE, int NFUSE>
__global__ __launch_bounds__(256, 2) void gemm_f16(
    const __half* __restrict__ A,
    const __half* __restrict__ B0, const __half* __restrict__ B1,
    const __half* __restrict__ B2,
    const float* __restrict__ bias0, const float* __restrict__ bias1,
    const float* __restrict__ bias2,
    float sc0, float sc1, float sc2,
    float* __restrict__ C,
    __half* __restrict__ Ch0, __half* __restrict__ Ch1,
    __half* __restrict__ Ch2,
    int M, int N)
{
    extern __shared__ char smemg[];
    __half* sbuf = (__half*)smemg;
    const uint32_t sb = smem_u32(smemg);

    const __half* B    = B0;
    const float*  bias = bias0;
    __half*       Ch   = Ch0;
    float         sc   = sc0;
    if (NFUSE > 1) {
        if (blockIdx.z == 1) { B = B1; bias = bias1; Ch = Ch1; sc = sc1; }
        else if (blockIdx.z == 2) { B = B2; bias = bias2; Ch = Ch2; sc = sc2; }
    }

    const int tid  = threadIdx.x;
    const int wid  = tid >> 5;
    const int m0   = blockIdx.y * BM;
    const int n0   = blockIdx.x * BN;
    const int wm   = (wid & 3) * 32;
    const int wn   = (wid >> 2) * 64;

    const __half* srcA = A + (size_t)m0 * GK;
    const __half* srcB = B + (size_t)n0 * GK;

    const int lrow0 = tid >> 3;
    const int lc16  = (tid & 7) * 8;

    auto load_chunk = [&](int kt, int buf) {
        const int kc = kt * BKC;
        const __half* ga = srcA + (size_t)lrow0 * GK + kc + lc16;
        const __half* gb = srcB + (size_t)lrow0 * GK + kc + lc16;
        uint32_t da = sb + buf * (2 * FTILE_BYTES) + (lrow0 * FSLD + lc16) * 2;
        uint32_t db = da + FTILE_BYTES;
        #pragma unroll
        for (int i = 0; i < 4; i++) {
            CP_ASYNC16(da + i * (32 * FSLD * 2), ga + (size_t)(i * 32) * GK);
            CP_ASYNC16(db + i * (32 * FSLD * 2), gb + (size_t)(i * 32) * GK);
        }
    };

    wmma::fragment<wmma::accumulator, 16, 16, 16, float> acc[2][4];
    #pragma unroll
    for (int t = 0; t < 2; t++)
        #pragma unroll
        for (int u = 0; u < 4; u++) wmma::fill_fragment(acc[t][u], 0.0f);

    load_chunk(0, 0);
    CP_ASYNC_COMMIT();
    CP_ASYNC_WAIT0();
    __syncthreads();

    for (int kt = 0; kt < NKC; kt++) {
        const int cur = kt & 1;
        if (kt + 1 < NKC) {
            load_chunk(kt + 1, cur ^ 1);
            CP_ASYNC_COMMIT();
        }

        const __half* pA = sbuf + cur * (2 * FTILE_ELEMS);
        const __half* pB = pA + FTILE_ELEMS;

        #pragma unroll
        for (int ks = 0; ks < 4; ks++) {
            wmma::fragment<wmma::matrix_a, 16, 16, 16, __half, wmma::row_major> ah[2];
            wmma::fragment<wmma::matrix_b, 16, 16, 16, __half, wmma::col_major> bh[4];
            #pragma unroll
            for (int t = 0; t < 2; t++)
                wmma::load_matrix_sync(ah[t], pA + (wm + t * 16) * FSLD + ks * 16, FSLD);
            #pragma unroll
            for (int u = 0; u < 4; u++)
                wmma::load_matrix_sync(bh[u], pB + (wn + u * 16) * FSLD + ks * 16, FSLD);
            #pragma unroll
            for (int t = 0; t < 2; t++)
                #pragma unroll
                for (int u = 0; u < 4; u++)
                    wmma::mma_sync(acc[t][u], ah[t], bh[u], acc[t][u]);
        }

        if (kt + 1 < NKC) CP_ASYNC_WAIT0();
        __syncthreads();
    }

    float* sC = (float*)smemg;
    const int CLD = 132;
    #pragma unroll
    for (int t = 0; t < 2; t++)
        #pragma unroll
        for (int u = 0; u < 4; u++)
            wmma::store_matrix_sync(sC + (wm + t * 16) * CLD + wn + u * 16,
                                    acc[t][u], CLD, wmma::mem_row_major);
    __syncthreads();

    #pragma unroll
    for (int i = 0; i < 16; i++) {
        const int flat4 = tid + i * 256;
        const int row = flat4 >> 5;
        const int c   = (flat4 & 31) * 4;
        float v0 = (sC[row * CLD + c + 0] + bias[n0 + c + 0]) * sc;
        float v1 = (sC[row * CLD + c + 1] + bias[n0 + c + 1]) * sc;
        float v2 = (sC[row * CLD + c + 2] + bias[n0 + c + 2]) * sc;
        float v3 = (sC[row * CLD + c + 3] + bias[n0 + c + 3]) * sc;
        if (MODE == 0) {
            *(float4*)(C + (size_t)(m0 + row) * N + n0 + c) =
                make_float4(v0, v1, v2, v3);
        } else {
            size_t idx = (size_t)blockIdx.x * (size_t)M * 128 + (size_t)(m0 + row) * 128 + c;
            uint2 ho;
            ho.x = pack_h2(__float2half(v0), __float2half(v1));
            ho.y = pack_h2(__float2half(v2), __float2half(v3));
            *(uint2*)(Ch + idx) = ho;
        }
    }
}

// ============================================================================
// fp16 WMMA flash attention (causal) — R13 structure (64-key tiles, 2 CTAs/SM)
// + fragment-level tile max (one fewer sync + no S max-pass)
// + base-2 softmax with pre-scaled Q (p = exp2(s - M), zero muls).
// SMEM: Q [128][136]h @0 (34816); KV bufs [64][136]h @34816+b*17408 (34816);
//       S fp32 [128][68] @69632 (34816), P fp16 aliased at S+64 halves offset;
//       sl @104448, swm @104960; total 105024. Epilogue O fp32 aliases @34816.
// ============================================================================
#define AQ_OFF  0
#define AKV_OFF 34816
#define KVBUF   17408
#define AS_OFF  69632
#define ASL_OFF 104448
#define ASW_OFF 104960
#define ATTN_SMEM 105024

__global__ __launch_bounds__(256, 2) void flash_attn_f16(
    const __half* __restrict__ Q16, const __half* __restrict__ K16,
    const __half* __restrict__ V16,
    __half* __restrict__ O16)
{
    extern __shared__ char smem[];
    const uint32_t sb = smem_u32(smem);

    __half* sQ  = (__half*)(smem + AQ_OFF);
    float*  sS  = (float*)(smem + AS_OFF);
    __half* sP  = (__half*)(smem + AS_OFF) + 64;   // aliased in S row padding
    float*  sl  = (float*)(smem + ASL_OFF);
    float*  swm = (float*)(smem + ASW_OFF);
    const int PLD = 136;

    const int tid = threadIdx.x;
    const int wid = tid >> 5;
    const int lane = tid & 31;
    const int qt  = gridDim.x - 1 - blockIdx.x;   // heavy CTAs first
    const int h   = blockIdx.y;
    const int ntiles = 2 * (qt + 1);

    const __half* Qh = Q16 + ((size_t)h * S_LEN + (size_t)qt * 128) * HD;
    const __half* Kh = K16 + (size_t)h * S_LEN * HD;
    const __half* Vh = V16 + (size_t)h * S_LEN * HD;

    auto loadQ = [&]() {
        #pragma unroll
        for (int rep = 0; rep < 8; rep++) {
            int id  = tid + rep * 256;
            int row = id >> 4, cc = (id & 15) * 8;
            CP_ASYNC16(sb + AQ_OFF + (row * 136 + cc) * 2, Qh + (size_t)row * HD + cc);
        }
    };
    auto loadKV = [&](const __half* Tp, int ktile, int buf) {
        const size_t base = (size_t)ktile * 64 * HD;
        #pragma unroll
        for (int rep = 0; rep < 4; rep++) {
            int id  = tid + rep * 256;
            int row = id >> 4, cc = (id & 15) * 8;
            CP_ASYNC16(sb + AKV_OFF + buf * KVBUF + (row * 136 + cc) * 2,
                       Tp + base + (size_t)row * HD + cc);
        }
    };

    loadQ();
    loadKV(Kh, 0, 0);
    CP_ASYNC_COMMIT();

    wmma::fragment<wmma::accumulator, 16, 16, 16, float> facc[2][4];
    #pragma unroll
    for (int t = 0; t < 2; t++)
        #pragma unroll
        for (int u = 0; u < 4; u++) wmma::fill_fragment(facc[t][u], 0.0f);
    float lrun = 0.0f;
    float Mrun = -1.0e30f;

    const int wm  = (wid & 3) * 32;       // warp q-rows
    const int wsn = (wid >> 2) * 32;      // warp key-cols (S phase)
    const int wn  = (wid >> 2) * 64;      // warp d-cols (PV phase)

    for (int kt = 0; kt < ntiles; kt++) {
        const int cur = kt & 1;
        __half* kvS = (__half*)(smem + AKV_OFF + cur * KVBUF);

        CP_ASYNC_WAIT0();
        __syncthreads();

        // ---- S = Q' K^T (Q pre-scaled by QKSCALE*log2e) ----
        float wmax = -1.0e30f;    // warp's tile max, from fragments
        {
            wmma::fragment<wmma::accumulator, 16, 16, 16, float> accs[2][2];
            #pragma unroll
            for (int t = 0; t < 2; t++)
                #pragma unroll
                for (int u = 0; u < 2; u++) wmma::fill_fragment(accs[t][u], 0.0f);

            #pragma unroll
            for (int ks = 0; ks < 8; ks++) {
                wmma::fragment<wmma::matrix_a, 16, 16, 16, __half, wmma::row_major> ah[2];
                wmma::fragment<wmma::matrix_b, 16, 16, 16, __half, wmma::col_major> bh[2];
                #pragma unroll
                for (int t = 0; t < 2; t++)
                    wmma::load_matrix_sync(ah[t], sQ + (wm + t * 16) * 136 + ks * 16, 136);
                #pragma unroll
                for (int u = 0; u < 2; u++)
                    wmma::load_matrix_sync(bh[u], kvS + (wsn + u * 16) * 136 + ks * 16, 136);
                #pragma unroll
                for (int t = 0; t < 2; t++)
                    #pragma unroll
                    for (int u = 0; u < 2; u++)
                        wmma::mma_sync(accs[t][u], ah[t], bh[u], accs[t][u]);
            }
            // fragment-level max (layout-agnostic) + store S
            #pragma unroll
            for (int t = 0; t < 2; t++)
                #pragma unroll
                for (int u = 0; u < 2; u++) {
                    #pragma unroll
                    for (int e = 0; e < accs[t][u].num_elements; e++)
                        wmax = fmaxf(wmax, accs[t][u].x[e]);
                    wmma::store_matrix_sync(sS + (wm + t * 16) * 68 + wsn + u * 16,
                                            accs[t][u], 68, wmma::mem_row_major);
                }
            #pragma unroll
            for (int o = 16; o > 0; o >>= 1)
                wmax = fmaxf(wmax, __shfl_xor_sync(0xffffffffu, wmax, o));
            if (lane == 0) swm[wid] = wmax;
        }
        __syncthreads();   // publishes S AND swm

        // ---- prefetch: V(kt) overwrites K(kt) in buf cur; K(kt+1) -> other buf
        loadKV(Vh, kt, cur);
        CP_ASYNC_COMMIT();
        if (kt + 1 < ntiles) loadKV(Kh, kt + 1, cur ^ 1);
        CP_ASYNC_COMMIT();

        float mfs = swm[0];
        #pragma unroll
        for (int w = 1; w < 8; w++) mfs = fmaxf(mfs, swm[w]);
        const float Mnew = fmaxf(Mrun, mfs);
        const float corr = exp2f(Mrun - Mnew);
        Mrun = Mnew;

        // ---- softmax: p = exp2(s - Mnew); reads S row to regs, P aliased ----
        {
            const int row = tid >> 1;
            const int c0  = (tid & 1) * 32;
            const int qglob = qt * 128 + row;
            const int kbase = kt * 64 + c0;
            const bool needMask = (kt >= 2 * qt);
            const float* Srow = sS + row * 68 + c0;

            float sv[32];
            #pragma unroll
            for (int j = 0; j < 32; j++) sv[j] = Srow[j];

            __half* Pr = sP + row * PLD + c0;
            float psum = 0.0f;
            #pragma unroll
            for (int j = 0; j < 32; j += 2) {
                float p0 = exp2f(sv[j]     - Mnew);
                float p1 = exp2f(sv[j + 1] - Mnew);
                if (needMask) {
                    if (kbase + j     > qglob) p0 = 0.0f;
                    if (kbase + j + 1 > qglob) p1 = 0.0f;
                }
                psum += p0 + p1;
                *(uint32_t*)(Pr + j) = pack_h2(__float2half(p0), __float2half(p1));
            }
            psum += __shfl_xor_sync(0xffffffffu, psum, 1);
            lrun = lrun * corr + psum;
        }

        // ---- rescale persistent accumulators (skip when corr==1) ----
        if (corr != 1.0f) {
            #pragma unroll
            for (int t = 0; t < 2; t++)
                #pragma unroll
                for (int u = 0; u < 4; u++)
                    #pragma unroll
                    for (int e = 0; e < facc[t][u].num_elements; e++)
                        facc[t][u].x[e] *= corr;
        }

        CP_ASYNC_WAIT1();
        __syncthreads();

        // ---- O += P V ----
        #pragma unroll
        for (int ks = 0; ks < 4; ks++) {
            wmma::fragment<wmma::matrix_a, 16, 16, 16, __half, wmma::row_major> pa[2];
            wmma::fragment<wmma::matrix_b, 16, 16, 16, __half, wmma::row_major> vb[4];
            #pragma unroll
            for (int t = 0; t < 2; t++)
                wmma::load_matrix_sync(pa[t], sP + (wm + t * 16) * PLD + ks * 16, PLD);
            #pragma unroll
            for (int u = 0; u < 4; u++)
                wmma::load_matrix_sync(vb[u], kvS + (ks * 16) * 136 + wn + u * 16, 136);
            #pragma unroll
            for (int t = 0; t < 2; t++)
                #pragma unroll
                for (int u = 0; u < 4; u++)
                    wmma::mma_sync(facc[t][u], pa[t], vb[u], facc[t][u]);
        }
    }

    CP_ASYNC_WAIT0();
    __syncthreads();

    // ---- epilogue: O = facc / lrun, fp16, write [s][DIM] ----
    float* sO = (float*)(smem + AKV_OFF);
    const int OLD = 132;
    #pragma unroll
    for (int t = 0; t < 2; t++)
        #pragma unroll
        for (int u = 0; u < 4; u++)
            wmma::store_matrix_sync(sO + (wm + t * 16) * OLD + wn + u * 16,
                                    facc[t][u], OLD, wmma::mem_row_major);
    if ((tid & 1) == 0) sl[tid >> 1] = lrun;
    __syncthreads();

    {
        const int row = tid >> 1;
        const int c0  = (tid & 1) * 64;
        const float inv = 1.0f / sl[row];
        const size_t dbase = (size_t)(qt * 128 + row) * DIM + (size_t)h * HD + c0;
        #pragma unroll
        for (int j = 0; j < 64; j += 2) {
            float o0 = sO[row * OLD + c0 + j]     * inv;
            float o1 = sO[row * OLD + c0 + j + 1] * inv;
            *(uint32_t*)(O16 + dbase + j) =
                pack_h2(__float2half(o0), __float2half(o1));
        }
    }
}

// ============================================================================
// launch
// ============================================================================
extern "C" void kernel_launch(void* const* d_in, const int* in_sizes, int n_in,
                              void* d_out, int out_size)
{
    const float* X  = (const float*)d_in[0];
    const float* Wq = (const float*)d_in[1];
    const float* bq = (const float*)d_in[2];
    const float* Wk = (const float*)d_in[3];
    const float* bk = (const float*)d_in[4];
    const float* Wv = (const float*)d_in[5];
    const float* bv = (const float*)d_in[6];
    const float* Wo = (const float*)d_in[7];
    const float* bo = (const float*)d_in[8];

    __half *Q16, *K16, *V16, *O16, *X16, *W16;
    cudaGetSymbolAddress((void**)&Q16, g_Q16);
    cudaGetSymbolAddress((void**)&K16, g_K16);
    cudaGetSymbolAddress((void**)&V16, g_V16);
    cudaGetSymbolAddress((void**)&O16, g_O16);
    cudaGetSymbolAddress((void**)&X16, g_X16);
    cudaGetSymbolAddress((void**)&W16, g_W16);

    const int NX4 = S_LEN * DIM / 4;
    const int NW4 = DIM * DIM / 4;

    split_h16<<<(NX4 + 255) / 256, 256>>>((const float4*)X, (uint2*)X16, NX4);
    dim3 gW((NW4 + 255) / 256, 4);
    split_h16_w4<<<gW, 256>>>((const float4*)Wq, (const float4*)Wk,
                              (const float4*)Wv, (const float4*)Wo,
                              (uint2*)W16, NW4);

    cudaFuncSetAttribute(gemm_f16<1, 3>,
        cudaFuncAttributeMaxDynamicSharedMemorySize, GEMM_SMEM);
    cudaFuncSetAttribute(gemm_f16<0, 1>,
        cudaFuncAttributeMaxDynamicSharedMemorySize, GEMM_SMEM);
    cudaFuncSetAttribute(flash_attn_f16,
        cudaFuncAttributeMaxDynamicSharedMemorySize, ATTN_SMEM);

    // Q pre-scale: (1/sqrt(128)) * log2(e)
    const float QSC = 0.08838834764831843f * 1.4426950408889634f;

    // Q + K + V projections fused: 1-term each; Q scaled
    dim3 gQKV(DIM / BN, S_LEN / BM, 3);
    gemm_f16<1, 3><<<gQKV, 256, GEMM_SMEM>>>(X16,
        W16 + 0 * (size_t)DIM * DIM, W16 + 1 * (size_t)DIM * DIM,
        W16 + 2 * (size_t)DIM * DIM,
        bq, bk, bv, QSC, 1.0f, 1.0f, nullptr, Q16, K16, V16, S_LEN, DIM);

    dim3 gAttn(S_LEN / 128, HEADS);
    flash_attn_f16<<<gAttn, 256, ATTN_SMEM>>>(Q16, K16, V16, O16);

    // O projection: 1-term
    dim3 gGemm(DIM / BN, S_LEN / BM);
    gemm_f16<0, 1><<<gGemm, 256, GEMM_SMEM>>>(O16,
        W16 + 3 * (size_t)DIM * DIM, nullptr, nullptr,
        bo, nullptr, nullptr, 1.0f, 1.0f, 1.0f,
        (float*)d_out, nullptr, nullptr, nullptr, S_LEN, DIM);
}

// round 16
// speedup vs baseline: 1.1412x; 1.0356x over previous
#include <cuda_runtime.h>
#include <cuda_fp16.h>
#include <mma.h>
#include <math_constants.h>
#include <cstdint>

using namespace nvcuda;

#define S_LEN 4096
#define DIM   2048
#define HEADS 16
#define HD    128
#define GK    2048
#define BM    128
#define BN    128
#define BKC   64
#define NKC   (GK / BKC)    // 32
#define FSLD  72            // gemm smem row stride (fp16)

// ---------------- scratch (allocation-free rule: __device__ globals) ----------
__device__ __half g_Q16[HEADS * S_LEN * HD];   // pre-scaled by QKSCALE*log2e
__device__ __half g_K16[HEADS * S_LEN * HD];
__device__ __half g_V16[HEADS * S_LEN * HD];
__device__ __half g_O16[S_LEN * DIM];
__device__ __half g_X16[S_LEN * DIM];
__device__ __half g_W16[4][DIM * DIM];

// ---------------- helpers ------------------------------------------------------
__device__ __forceinline__ uint32_t smem_u32(const void* p) {
    uint32_t a;
    asm("{ .reg .u64 t; cvta.to.shared.u64 t, %1; cvt.u32.u64 %0, t; }"
        : "=r"(a) : "l"(p));
    return a;
}
#define CP_ASYNC16(dst_u32, src_ptr) \
    asm volatile("cp.async.cg.shared.global [%0], [%1], 16;" \
        :: "r"(dst_u32), "l"(src_ptr) : "memory")
#define CP_ASYNC_COMMIT() asm volatile("cp.async.commit_group;" ::: "memory")
#define CP_ASYNC_WAIT0()  asm volatile("cp.async.wait_group 0;" ::: "memory")
#define CP_ASYNC_WAIT1()  asm volatile("cp.async.wait_group 1;" ::: "memory")

__device__ __forceinline__ uint32_t pack_h2(__half a, __half b) {
    __half2 t = __halves2half2(a, b);
    return *(uint32_t*)&t;
}

// ============================================================================
// fused 5-way split: slice 0 = X (2 chunks/thread), slices 1..4 = weights
// ============================================================================
__global__ void split_all(const float4* __restrict__ X,
                          const float4* __restrict__ s1,
                          const float4* __restrict__ s2,
                          const float4* __restrict__ s3,
                          const float4* __restrict__ s4,
                          uint2* __restrict__ dX, uint2* __restrict__ dW,
                          int nW4) {
    int i = blockIdx.x * 256 + threadIdx.x;
    if (i >= nW4) return;
    if (blockIdx.y == 0) {
        #pragma unroll
        for (int r = 0; r < 2; r++) {
            int ii = i + r * nW4;
            float4 v = X[ii];
            uint2 ho;
            ho.x = pack_h2(__float2half(v.x), __float2half(v.y));
            ho.y = pack_h2(__float2half(v.z), __float2half(v.w));
            dX[ii] = ho;
        }
    } else {
        const float4* srcs[4] = {s1, s2, s3, s4};
        float4 v = srcs[blockIdx.y - 1][i];
        uint2 ho;
        ho.x = pack_h2(__float2half(v.x), __float2half(v.y));
        ho.y = pack_h2(__float2half(v.z), __float2half(v.w));
        dW[(size_t)(blockIdx.y - 1) * nW4 + i] = ho;
    }
}

// ============================================================================
// fp16 WMMA GEMM (1-term): C = (A * B^T + bias) * scale   — 2 CTAs/SM
// ============================================================================
#define FTILE_ELEMS (128 * FSLD)
#define FTILE_BYTES (FTILE_ELEMS * 2)          // 18432
#define GEMM_SMEM   (2 * 2 * FTILE_BYTES)      // 73728

template <int MODE, int NFUSE>
__global__ __launch_bounds__(256, 2) void gemm_f16(
    const __half* __restrict__ A,
    const __half* __restrict__ B0, const __half* __restrict__ B1,
    const __half* __restrict__ B2,
    const float* __restrict__ bias0, const float* __restrict__ bias1,
    const float* __restrict__ bias2,
    float sc0, float sc1, float sc2,
    float* __restrict__ C,
    __half* __restrict__ Ch0, __half* __restrict__ Ch1,
    __half* __restrict__ Ch2,
    int M, int N)
{
    extern __shared__ char smemg[];
    __half* sbuf = (__half*)smemg;
    const uint32_t sb = smem_u32(smemg);

    const __half* B    = B0;
    const float*  bias = bias0;
    __half*       Ch   = Ch0;
    float         sc   = sc0;
    if (NFUSE > 1) {
        if (blockIdx.z == 1) { B = B1; bias = bias1; Ch = Ch1; sc = sc1; }
        else if (blockIdx.z == 2) { B = B2; bias = bias2; Ch = Ch2; sc = sc2; }
    }

    const int tid  = threadIdx.x;
    const int wid  = tid >> 5;
    const int m0   = blockIdx.y * BM;
    const int n0   = blockIdx.x * BN;
    const int wm   = (wid & 3) * 32;
    const int wn   = (wid >> 2) * 64;

    const __half* srcA = A + (size_t)m0 * GK;
    const __half* srcB = B + (size_t)n0 * GK;

    const int lrow0 = tid >> 3;
    const int lc16  = (tid & 7) * 8;

    auto load_chunk = [&](int kt, int buf) {
        const int kc = kt * BKC;
        const __half* ga = srcA + (size_t)lrow0 * GK + kc + lc16;
        const __half* gb = srcB + (size_t)lrow0 * GK + kc + lc16;
        uint32_t da = sb + buf * (2 * FTILE_BYTES) + (lrow0 * FSLD + lc16) * 2;
        uint32_t db = da + FTILE_BYTES;
        #pragma unroll
        for (int i = 0; i < 4; i++) {
            CP_ASYNC16(da + i * (32 * FSLD * 2), ga + (size_t)(i * 32) * GK);
            CP_ASYNC16(db + i * (32 * FSLD * 2), gb + (size_t)(i * 32) * GK);
        }
    };

    wmma::fragment<wmma::accumulator, 16, 16, 16, float> acc[2][4];
    #pragma unroll
    for (int t = 0; t < 2; t++)
        #pragma unroll
        for (int u = 0; u < 4; u++) wmma::fill_fragment(acc[t][u], 0.0f);

    load_chunk(0, 0);
    CP_ASYNC_COMMIT();
    CP_ASYNC_WAIT0();
    __syncthreads();

    for (int kt = 0; kt < NKC; kt++) {
        const int cur = kt & 1;
        if (kt + 1 < NKC) {
            load_chunk(kt + 1, cur ^ 1);
            CP_ASYNC_COMMIT();
        }

        const __half* pA = sbuf + cur * (2 * FTILE_ELEMS);
        const __half* pB = pA + FTILE_ELEMS;

        #pragma unroll
        for (int ks = 0; ks < 4; ks++) {
            wmma::fragment<wmma::matrix_a, 16, 16, 16, __half, wmma::row_major> ah[2];
            wmma::fragment<wmma::matrix_b, 16, 16, 16, __half, wmma::col_major> bh[4];
            #pragma unroll
            for (int t = 0; t < 2; t++)
                wmma::load_matrix_sync(ah[t], pA + (wm + t * 16) * FSLD + ks * 16, FSLD);
            #pragma unroll
            for (int u = 0; u < 4; u++)
                wmma::load_matrix_sync(bh[u], pB + (wn + u * 16) * FSLD + ks * 16, FSLD);
            #pragma unroll
            for (int t = 0; t < 2; t++)
                #pragma unroll
                for (int u = 0; u < 4; u++)
                    wmma::mma_sync(acc[t][u], ah[t], bh[u], acc[t][u]);
        }

        if (kt + 1 < NKC) CP_ASYNC_WAIT0();
        __syncthreads();
    }

    float* sC = (float*)smemg;
    const int CLD = 132;
    #pragma unroll
    for (int t = 0; t < 2; t++)
        #pragma unroll
        for (int u = 0; u < 4; u++)
            wmma::store_matrix_sync(sC + (wm + t * 16) * CLD + wn + u * 16,
                                    acc[t][u], CLD, wmma::mem_row_major);
    __syncthreads();

    #pragma unroll
    for (int i = 0; i < 16; i++) {
        const int flat4 = tid + i * 256;
        const int row = flat4 >> 5;
        const int c   = (flat4 & 31) * 4;
        float v0 = (sC[row * CLD + c + 0] + bias[n0 + c + 0]) * sc;
        float v1 = (sC[row * CLD + c + 1] + bias[n0 + c + 1]) * sc;
        float v2 = (sC[row * CLD + c + 2] + bias[n0 + c + 2]) * sc;
        float v3 = (sC[row * CLD + c + 3] + bias[n0 + c + 3]) * sc;
        if (MODE == 0) {
            *(float4*)(C + (size_t)(m0 + row) * N + n0 + c) =
                make_float4(v0, v1, v2, v3);
        } else {
            size_t idx = (size_t)blockIdx.x * (size_t)M * 128 + (size_t)(m0 + row) * 128 + c;
            uint2 ho;
            ho.x = pack_h2(__float2half(v0), __float2half(v1));
            ho.y = pack_h2(__float2half(v2), __float2half(v3));
            *(uint2*)(Ch + idx) = ho;
        }
    }
}

// ============================================================================
// fp16 WMMA flash attention (causal) — R15 structure + ex2.approx.f16x2 softmax
// ============================================================================
#define AQ_OFF  0
#define AKV_OFF 34816
#define KVBUF   17408
#define AS_OFF  69632
#define ASL_OFF 104448
#define ASW_OFF 104960
#define ATTN_SMEM 105024

__global__ __launch_bounds__(256, 2) void flash_attn_f16(
    const __half* __restrict__ Q16, const __half* __restrict__ K16,
    const __half* __restrict__ V16,
    __half* __restrict__ O16)
{
    extern __shared__ char smem[];
    const uint32_t sb = smem_u32(smem);

    __half* sQ  = (__half*)(smem + AQ_OFF);
    float*  sS  = (float*)(smem + AS_OFF);
    __half* sP  = (__half*)(smem + AS_OFF) + 64;   // aliased in S row padding
    float*  sl  = (float*)(smem + ASL_OFF);
    float*  swm = (float*)(smem + ASW_OFF);
    const int PLD = 136;

    const int tid = threadIdx.x;
    const int wid = tid >> 5;
    const int lane = tid & 31;
    const int qt  = gridDim.x - 1 - blockIdx.x;   // heavy CTAs first
    const int h   = blockIdx.y;
    const int ntiles = 2 * (qt + 1);

    const __half* Qh = Q16 + ((size_t)h * S_LEN + (size_t)qt * 128) * HD;
    const __half* Kh = K16 + (size_t)h * S_LEN * HD;
    const __half* Vh = V16 + (size_t)h * S_LEN * HD;

    auto loadQ = [&]() {
        #pragma unroll
        for (int rep = 0; rep < 8; rep++) {
            int id  = tid + rep * 256;
            int row = id >> 4, cc = (id & 15) * 8;
            CP_ASYNC16(sb + AQ_OFF + (row * 136 + cc) * 2, Qh + (size_t)row * HD + cc);
        }
    };
    auto loadKV = [&](const __half* Tp, int ktile, int buf) {
        const size_t base = (size_t)ktile * 64 * HD;
        #pragma unroll
        for (int rep = 0; rep < 4; rep++) {
            int id  = tid + rep * 256;
            int row = id >> 4, cc = (id & 15) * 8;
            CP_ASYNC16(sb + AKV_OFF + buf * KVBUF + (row * 136 + cc) * 2,
                       Tp + base + (size_t)row * HD + cc);
        }
    };

    loadQ();
    loadKV(Kh, 0, 0);
    CP_ASYNC_COMMIT();

    wmma::fragment<wmma::accumulator, 16, 16, 16, float> facc[2][4];
    #pragma unroll
    for (int t = 0; t < 2; t++)
        #pragma unroll
        for (int u = 0; u < 4; u++) wmma::fill_fragment(facc[t][u], 0.0f);
    float lrun = 0.0f;
    float Mrun = -1.0e30f;

    const int wm  = (wid & 3) * 32;       // warp q-rows
    const int wsn = (wid >> 2) * 32;      // warp key-cols (S phase)
    const int wn  = (wid >> 2) * 64;      // warp d-cols (PV phase)

    for (int kt = 0; kt < ntiles; kt++) {
        const int cur = kt & 1;
        __half* kvS = (__half*)(smem + AKV_OFF + cur * KVBUF);

        CP_ASYNC_WAIT0();
        __syncthreads();

        // ---- S = Q' K^T (Q pre-scaled by QKSCALE*log2e) ----
        float wmax = -1.0e30f;
        {
            wmma::fragment<wmma::accumulator, 16, 16, 16, float> accs[2][2];
            #pragma unroll
            for (int t = 0; t < 2; t++)
                #pragma unroll
                for (int u = 0; u < 2; u++) wmma::fill_fragment(accs[t][u], 0.0f);

            #pragma unroll
            for (int ks = 0; ks < 8; ks++) {
                wmma::fragment<wmma::matrix_a, 16, 16, 16, __half, wmma::row_major> ah[2];
                wmma::fragment<wmma::matrix_b, 16, 16, 16, __half, wmma::col_major> bh[2];
                #pragma unroll
                for (int t = 0; t < 2; t++)
                    wmma::load_matrix_sync(ah[t], sQ + (wm + t * 16) * 136 + ks * 16, 136);
                #pragma unroll
                for (int u = 0; u < 2; u++)
                    wmma::load_matrix_sync(bh[u], kvS + (wsn + u * 16) * 136 + ks * 16, 136);
                #pragma unroll
                for (int t = 0; t < 2; t++)
                    #pragma unroll
                    for (int u = 0; u < 2; u++)
                        wmma::mma_sync(accs[t][u], ah[t], bh[u], accs[t][u]);
            }
            #pragma unroll
            for (int t = 0; t < 2; t++)
                #pragma unroll
                for (int u = 0; u < 2; u++) {
                    #pragma unroll
                    for (int e = 0; e < accs[t][u].num_elements; e++)
                        wmax = fmaxf(wmax, accs[t][u].x[e]);
                    wmma::store_matrix_sync(sS + (wm + t * 16) * 68 + wsn + u * 16,
                                            accs[t][u], 68, wmma::mem_row_major);
                }
            #pragma unroll
            for (int o = 16; o > 0; o >>= 1)
                wmax = fmaxf(wmax, __shfl_xor_sync(0xffffffffu, wmax, o));
            if (lane == 0) swm[wid] = wmax;
        }
        __syncthreads();   // publishes S AND swm

        // ---- prefetch: V(kt) overwrites K(kt) in buf cur; K(kt+1) -> other buf
        loadKV(Vh, kt, cur);
        CP_ASYNC_COMMIT();
        if (kt + 1 < ntiles) loadKV(Kh, kt + 1, cur ^ 1);
        CP_ASYNC_COMMIT();

        float mfs = swm[0];
        #pragma unroll
        for (int w = 1; w < 8; w++) mfs = fmaxf(mfs, swm[w]);
        const float Mnew = fmaxf(Mrun, mfs);
        const float corr = exp2f(Mrun - Mnew);
        Mrun = Mnew;

        // ---- softmax: p = ex2.approx.f16x2(s - Mnew) pairs ----
        {
            const int row = tid >> 1;
            const int c0  = (tid & 1) * 32;
            const int qglob = qt * 128 + row;
            const int kbase = kt * 64 + c0;
            const bool needMask = (kt >= 2 * qt);
            const float* Srow = sS + row * 68 + c0;

            float sv[32];
            #pragma unroll
            for (int j = 0; j < 32; j++) sv[j] = Srow[j];
            if (needMask) {
                #pragma unroll
                for (int j = 0; j < 32; j++)
                    if (kbase + j > qglob) sv[j] = -30000.0f;
            }

            __half* Pr = sP + row * PLD + c0;
            float psum = 0.0f;
            #pragma unroll
            for (int j = 0; j < 32; j += 2) {
                __half2 xin = __floats2half2_rn(sv[j] - Mnew, sv[j + 1] - Mnew);
                uint32_t xi = *(uint32_t*)&xin;
                uint32_t pi;
                asm("ex2.approx.f16x2 %0, %1;" : "=r"(pi) : "r"(xi));
                *(uint32_t*)(Pr + j) = pi;
                __half2 p2 = *(__half2*)&pi;
                float2 pf = __half22float2(p2);
                psum += pf.x + pf.y;
            }
            psum += __shfl_xor_sync(0xffffffffu, psum, 1);
            lrun = lrun * corr + psum;
        }

        // ---- rescale persistent accumulators (skip when corr==1) ----
        if (corr != 1.0f) {
            #pragma unroll
            for (int t = 0; t < 2; t++)
                #pragma unroll
                for (int u = 0; u < 4; u++)
                    #pragma unroll
                    for (int e = 0; e < facc[t][u].num_elements; e++)
                        facc[t][u].x[e] *= corr;
        }

        CP_ASYNC_WAIT1();
        __syncthreads();

        // ---- O += P V ----
        #pragma unroll
        for (int ks = 0; ks < 4; ks++) {
            wmma::fragment<wmma::matrix_a, 16, 16, 16, __half, wmma::row_major> pa[2];
            wmma::fragment<wmma::matrix_b, 16, 16, 16, __half, wmma::row_major> vb[4];
            #pragma unroll
            for (int t = 0; t < 2; t++)
                wmma::load_matrix_sync(pa[t], sP + (wm + t * 16) * PLD + ks * 16, PLD);
            #pragma unroll
            for (int u = 0; u < 4; u++)
                wmma::load_matrix_sync(vb[u], kvS + (ks * 16) * 136 + wn + u * 16, 136);
            #pragma unroll
            for (int t = 0; t < 2; t++)
                #pragma unroll
                for (int u = 0; u < 4; u++)
                    wmma::mma_sync(facc[t][u], pa[t], vb[u], facc[t][u]);
        }
    }

    CP_ASYNC_WAIT0();
    __syncthreads();

    // ---- epilogue: O = facc / lrun, fp16, write [s][DIM] ----
    float* sO = (float*)(smem + AKV_OFF);
    const int OLD = 132;
    #pragma unroll
    for (int t = 0; t < 2; t++)
        #pragma unroll
        for (int u = 0; u < 4; u++)
            wmma::store_matrix_sync(sO + (wm + t * 16) * OLD + wn + u * 16,
                                    facc[t][u], OLD, wmma::mem_row_major);
    if ((tid & 1) == 0) sl[tid >> 1] = lrun;
    __syncthreads();

    {
        const int row = tid >> 1;
        const int c0  = (tid & 1) * 64;
        const float inv = 1.0f / sl[row];
        const size_t dbase = (size_t)(qt * 128 + row) * DIM + (size_t)h * HD + c0;
        #pragma unroll
        for (int j = 0; j < 64; j += 2) {
            float o0 = sO[row * OLD + c0 + j]     * inv;
            float o1 = sO[row * OLD + c0 + j + 1] * inv;
            *(uint32_t*)(O16 + dbase + j) =
                pack_h2(__float2half(o0), __float2half(o1));
        }
    }
}

// ============================================================================
// launch
// ============================================================================
extern "C" void kernel_launch(void* const* d_in, const int* in_sizes, int n_in,
                              void* d_out, int out_size)
{
    const float* X  = (const float*)d_in[0];
    const float* Wq = (const float*)d_in[1];
    const float* bq = (const float*)d_in[2];
    const float* Wk = (const float*)d_in[3];
    const float* bk = (const float*)d_in[4];
    const float* Wv = (const float*)d_in[5];
    const float* bv = (const float*)d_in[6];
    const float* Wo = (const float*)d_in[7];
    const float* bo = (const float*)d_in[8];

    __half *Q16, *K16, *V16, *O16, *X16, *W16;
    cudaGetSymbolAddress((void**)&Q16, g_Q16);
    cudaGetSymbolAddress((void**)&K16, g_K16);
    cudaGetSymbolAddress((void**)&V16, g_V16);
    cudaGetSymbolAddress((void**)&O16, g_O16);
    cudaGetSymbolAddress((void**)&X16, g_X16);
    cudaGetSymbolAddress((void**)&W16, g_W16);

    const int NW4 = DIM * DIM / 4;

    dim3 gS((NW4 + 255) / 256, 5);
    split_all<<<gS, 256>>>((const float4*)X,
                           (const float4*)Wq, (const float4*)Wk,
                           (const float4*)Wv, (const float4*)Wo,
                           (uint2*)X16, (uint2*)W16, NW4);

    cudaFuncSetAttribute(gemm_f16<1, 3>,
        cudaFuncAttributeMaxDynamicSharedMemorySize, GEMM_SMEM);
    cudaFuncSetAttribute(gemm_f16<0, 1>,
        cudaFuncAttributeMaxDynamicSharedMemorySize, GEMM_SMEM);
    cudaFuncSetAttribute(flash_attn_f16,
        cudaFuncAttributeMaxDynamicSharedMemorySize, ATTN_SMEM);

    // Q pre-scale: (1/sqrt(128)) * log2(e)
    const float QSC = 0.08838834764831843f * 1.4426950408889634f;

    dim3 gQKV(DIM / BN, S_LEN / BM, 3);
    gemm_f16<1, 3><<<gQKV, 256, GEMM_SMEM>>>(X16,
        W16 + 0 * (size_t)DIM * DIM, W16 + 1 * (size_t)DIM * DIM,
        W16 + 2 * (size_t)DIM * DIM,
        bq, bk, bv, QSC, 1.0f, 1.0f, nullptr, Q16, K16, V16, S_LEN, DIM);

    dim3 gAttn(S_LEN / 128, HEADS);
    flash_attn_f16<<<gAttn, 256, ATTN_SMEM>>>(Q16, K16, V16, O16);

    dim3 gGemm(DIM / BN, S_LEN / BM);
    gemm_f16<0, 1><<<gGemm, 256, GEMM_SMEM>>>(O16,
        W16 + 3 * (size_t)DIM * DIM, nullptr, nullptr,
        bo, nullptr, nullptr, 1.0f, 1.0f, 1.0f,
        (float*)d_out, nullptr, nullptr, nullptr, S_LEN, DIM);
}